// round 1
// baseline (speedup 1.0000x reference)
#include <cuda_runtime.h>
#include <cstdint>

// LIF neuron scan: x[T=8, B, C, H, W] fp32 -> spikes {-1,0,+1} fp32.
// tau = 5/3; V' = V + (-V/tau + x); spike if |V'| >= 1; hard reset to 0.
// Each thread owns 4 spatial positions (float4) and iterates the T=8
// recurrence privately. All 8 timestep loads are independent of V, so we
// batch them first for MLP=8, then compute, then store.

static constexpr int T_STEPS = 8;

__device__ __forceinline__ void lif_step(float& V, float xv, float& o) {
    const float TAU = 5.0f / 3.0f;                 // fp32-rounded, matches jnp
    float dv = __fdiv_rn(-V, TAU) + xv;            // exact IEEE div even w/ fast-math
    float vn = V + dv;
    float pos = (vn >=  1.0f) ? 1.0f : 0.0f;
    float neg = (vn <= -1.0f) ? 1.0f : 0.0f;
    o = pos - neg;
    V = (pos + neg > 0.0f) ? 0.0f : vn;            // hard reset where spiked
}

__global__ __launch_bounds__(256)
void lif_kernel(const float4* __restrict__ x, float4* __restrict__ y, int n4) {
    int i = blockIdx.x * blockDim.x + threadIdx.x;
    if (i >= n4) return;

    // Batched prefetch: 8 independent float4 loads in flight (MLP=8).
    float4 xs[T_STEPS];
#pragma unroll
    for (int t = 0; t < T_STEPS; ++t)
        xs[t] = x[t * n4 + i];

    float4 V = make_float4(0.f, 0.f, 0.f, 0.f);
#pragma unroll
    for (int t = 0; t < T_STEPS; ++t) {
        float4 o;
        lif_step(V.x, xs[t].x, o.x);
        lif_step(V.y, xs[t].y, o.y);
        lif_step(V.z, xs[t].z, o.z);
        lif_step(V.w, xs[t].w, o.w);
        y[t * n4 + i] = o;
    }
}

extern "C" void kernel_launch(void* const* d_in, const int* in_sizes, int n_in,
                              void* d_out, int out_size) {
    const float* x = (const float*)d_in[0];
    float* y = (float*)d_out;

    int total = in_sizes[0];          // T*B*C*H*W = 33,554,432
    int n_spatial = total / T_STEPS;  // 4,194,304
    int n4 = n_spatial / 4;           // 1,048,576 float4 lanes

    int threads = 256;
    int blocks = (n4 + threads - 1) / threads;
    lif_kernel<<<blocks, threads>>>((const float4*)x, (float4*)y, n4);
}

// round 2
// speedup vs baseline: 1.3978x; 1.3978x over previous
#include <cuda_runtime.h>
#include <cstdint>

// LIF neuron scan: x[T=8, B, C, H, W] fp32 -> spikes {-1,0,+1} fp32.
// tau = 5/3; V' = V + (-V/tau + x); spike if |V'| >= 1; hard reset to 0.
//
// Division by the constant tau is done with Markstein's correctly-rounded
// 3-op sequence (mul + 2 fma), which is bit-identical to IEEE RN division
// for all normal inputs -- replaces ptxas's ~15-instruction div expansion
// that made round-1 issue/ALU-bound (alu pipe 69.5%, DRAM only 46%).

static constexpr int T_STEPS = 8;

__device__ __forceinline__ void lif_step(float& V, float xv, float& o) {
    constexpr float TAU = 5.0f / 3.0f;        // fl(5/3), matches jnp float32
    constexpr float R   = 1.0f / TAU;         // RN(1/fl(5/3)), compile-time

    // q = RN((-V) / TAU) via Markstein: correctly rounded for normal operands.
    float a  = -V;
    float q0 = __fmul_rn(a, R);
    float e  = __fmaf_rn(-TAU, q0, a);
    float q  = __fmaf_rn(e, R, q0);

    float dv = __fadd_rn(q, xv);              // dv = -V/tau + x
    float vn = __fadd_rn(V, dv);              // V_new = V + dv

    bool p = (vn >=  1.0f);
    bool n = (vn <= -1.0f);
    o = p ? 1.0f : (n ? -1.0f : 0.0f);
    V = (p || n) ? 0.0f : vn;                 // hard reset where spiked
}

__global__ __launch_bounds__(256)
void lif_kernel(const float4* __restrict__ x, float4* __restrict__ y, int n4) {
    int i = blockIdx.x * blockDim.x + threadIdx.x;
    if (i >= n4) return;

    // Batched prefetch: 8 independent float4 loads in flight (MLP=8).
    float4 xs[T_STEPS];
#pragma unroll
    for (int t = 0; t < T_STEPS; ++t)
        xs[t] = x[t * n4 + i];

    float4 V = make_float4(0.f, 0.f, 0.f, 0.f);
#pragma unroll
    for (int t = 0; t < T_STEPS; ++t) {
        float4 o;
        lif_step(V.x, xs[t].x, o.x);
        lif_step(V.y, xs[t].y, o.y);
        lif_step(V.z, xs[t].z, o.z);
        lif_step(V.w, xs[t].w, o.w);
        y[t * n4 + i] = o;
    }
}

extern "C" void kernel_launch(void* const* d_in, const int* in_sizes, int n_in,
                              void* d_out, int out_size) {
    const float* x = (const float*)d_in[0];
    float* y = (float*)d_out;

    int total = in_sizes[0];          // T*B*C*H*W = 33,554,432
    int n_spatial = total / T_STEPS;  // 4,194,304
    int n4 = n_spatial / 4;           // 1,048,576 float4 lanes

    int threads = 256;
    int blocks = (n4 + threads - 1) / threads;
    lif_kernel<<<blocks, threads>>>((const float4*)x, (float4*)y, n4);
}

// round 3
// speedup vs baseline: 1.4162x; 1.0131x over previous
#include <cuda_runtime.h>
#include <cstdint>

// LIF neuron scan: x[T=8, B, C, H, W] fp32 -> spikes {-1,0,+1} fp32.
// tau = 5/3; V' = V + (-V/tau + x); spike if |V'| >= 1; hard reset to 0.
//
// R3 changes vs R2 (44.5us):
//  - packed f32x2 math (Blackwell): 5 recurrence ops per PAIR of lanes,
//    bit-identical RN rounding per lane (Markstein div-by-const preserved).
//  - spike logic: single FSETP on |vn| + copysign/select (was 2 compares).
//  - __ldcs/__stcs streaming hints: zero-reuse 268MB stream.

static constexpr int T_STEPS = 8;

using u64 = unsigned long long;

__device__ __forceinline__ u64 f32x2_pack(float lo, float hi) {
    u64 r;
    asm("mov.b64 %0, {%1, %2};" : "=l"(r) : "f"(lo), "f"(hi));
    return r;
}
__device__ __forceinline__ void f32x2_unpack(u64 v, float& lo, float& hi) {
    asm("mov.b64 {%0, %1}, %2;" : "=f"(lo), "=f"(hi) : "l"(v));
}

// vn = V + ((x - RN(V/TAU)))  computed per-lane exactly as the scalar RN
// sequence: q0=V*R; e=fma(-TAU,q0,V); q=fma(e,R,q0)  [Markstein => q=RN(V/TAU)]
// dv=fma(q,-1,x)=RN(x-q);  vn=RN(V+dv).
__device__ __forceinline__ u64 lif_vn_pair(u64 Vp, u64 xp,
                                           u64 R2, u64 nT2, u64 m1) {
    u64 q0, e, q, dv, vn;
    asm("mul.rn.f32x2 %0, %1, %2;"     : "=l"(q0) : "l"(Vp), "l"(R2));
    asm("fma.rn.f32x2 %0, %1, %2, %3;" : "=l"(e)  : "l"(nT2), "l"(q0), "l"(Vp));
    asm("fma.rn.f32x2 %0, %1, %2, %3;" : "=l"(q)  : "l"(e),  "l"(R2), "l"(q0));
    asm("fma.rn.f32x2 %0, %1, %2, %3;" : "=l"(dv) : "l"(q),  "l"(m1), "l"(xp));
    asm("add.rn.f32x2 %0, %1, %2;"     : "=l"(vn) : "l"(Vp), "l"(dv));
    return vn;
}

__device__ __forceinline__ void spike(float vn, float& o, float& Vn) {
    bool p = fabsf(vn) >= 1.0f;            // |src| modifier on FSETP: free
    o  = p ? copysignf(1.0f, vn) : 0.0f;   // LOP3 + FSEL
    Vn = p ? 0.0f : vn;                    // FSEL
}

__global__ __launch_bounds__(256)
void lif_kernel(const float4* __restrict__ x, float4* __restrict__ y, int n4) {
    int i = blockIdx.x * blockDim.x + threadIdx.x;
    if (i >= n4) return;

    constexpr float TAU = 5.0f / 3.0f;     // fl(5/3), matches jnp float32
    constexpr float R   = 1.0f / TAU;      // RN(1/fl(5/3)), compile-time
    const u64 R2  = f32x2_pack(R, R);
    const u64 nT2 = f32x2_pack(-TAU, -TAU);
    const u64 m1  = f32x2_pack(-1.0f, -1.0f);

    // Batched streaming prefetch: 8 independent LDG.128.CS in flight.
    float4 xs[T_STEPS];
#pragma unroll
    for (int t = 0; t < T_STEPS; ++t)
        xs[t] = __ldcs(&x[t * n4 + i]);

    u64 Va = f32x2_pack(0.f, 0.f);
    u64 Vb = Va;

#pragma unroll
    for (int t = 0; t < T_STEPS; ++t) {
        u64 xa = f32x2_pack(xs[t].x, xs[t].y);
        u64 xb = f32x2_pack(xs[t].z, xs[t].w);

        u64 vna = lif_vn_pair(Va, xa, R2, nT2, m1);
        u64 vnb = lif_vn_pair(Vb, xb, R2, nT2, m1);

        float v0, v1, v2, v3;
        f32x2_unpack(vna, v0, v1);
        f32x2_unpack(vnb, v2, v3);

        float4 o;
        float w0, w1, w2, w3;
        spike(v0, o.x, w0);
        spike(v1, o.y, w1);
        spike(v2, o.z, w2);
        spike(v3, o.w, w3);

        Va = f32x2_pack(w0, w1);
        Vb = f32x2_pack(w2, w3);

        __stcs(&y[t * n4 + i], o);         // STG.128 evict-first
    }
}

extern "C" void kernel_launch(void* const* d_in, const int* in_sizes, int n_in,
                              void* d_out, int out_size) {
    const float* x = (const float*)d_in[0];
    float* y = (float*)d_out;

    int total = in_sizes[0];          // T*B*C*H*W = 33,554,432
    int n_spatial = total / T_STEPS;  // 4,194,304
    int n4 = n_spatial / 4;           // 1,048,576 float4 lanes

    int threads = 256;
    int blocks = (n4 + threads - 1) / threads;
    lif_kernel<<<blocks, threads>>>((const float4*)x, (float4*)y, n4);
}